// round 3
// baseline (speedup 1.0000x reference)
#include <cuda_runtime.h>
#include <cuda_fp16.h>
#include <cstdint>

// ============================================================================
// Problem dims: out[M,N] = scale * x[M,K] @ W[N,K]^T + bias[N]
// ============================================================================
#define KTOT 4096
#define MTOT 8192   // 4 * 2048
#define NTOT 11008

constexpr int BM = 128, BN = 256, BK = 64;
constexpr int KCHUNKS = KTOT / BK;     // 64
constexpr int NTM = MTOT / BM;         // 64
constexpr int NTN = NTOT / BN;         // 43
constexpr int NSTAGE = 3;

constexpr int A_BYTES = BM * BK * 2;            // 16384
constexpr int B_BYTES = BN * BK * 2;            // 32768
constexpr int STAGE_BYTES = A_BYTES + B_BYTES;  // 49152
constexpr int SMEM_TOTAL = NSTAGE * STAGE_BYTES;// 147456

// ============================================================================
// Device scratch (no cudaMalloc allowed)
// ============================================================================
static __device__ __half g_xh[(size_t)MTOT * KTOT];   // 64 MB
static __device__ __half g_wh[(size_t)NTOT * KTOT];   // 86 MB

// ============================================================================
// Helpers (plain sm_103 PTX only: cp.async / ldmatrix / mma.sync)
// ============================================================================
__device__ __forceinline__ uint32_t smem_u32(const void* p) {
    return (uint32_t)__cvta_generic_to_shared(p);
}

__device__ __forceinline__ uint32_t sw128(uint32_t o) {
    return o ^ ((o >> 3) & 0x70);
}

__device__ __forceinline__ void cp16(uint32_t dst, const void* src) {
    asm volatile("cp.async.cg.shared.global [%0], [%1], 16;\n"
                 :: "r"(dst), "l"(src) : "memory");
}
#define CP_COMMIT() asm volatile("cp.async.commit_group;\n" ::: "memory")
#define CP_WAIT(N)  asm volatile("cp.async.wait_group %0;\n" :: "n"(N) : "memory")

__device__ __forceinline__ void ldsm4(uint32_t r[4], uint32_t addr) {
    asm volatile("ldmatrix.sync.aligned.m8n8.x4.shared.b16 {%0,%1,%2,%3}, [%4];"
                 : "=r"(r[0]), "=r"(r[1]), "=r"(r[2]), "=r"(r[3]) : "r"(addr));
}

__device__ __forceinline__ void mma16816(float c[4], const uint32_t a[4],
                                         uint32_t b0, uint32_t b1) {
    asm volatile(
        "mma.sync.aligned.m16n8k16.row.col.f32.f16.f16.f32 "
        "{%0,%1,%2,%3}, {%4,%5,%6,%7}, {%8,%9}, {%0,%1,%2,%3};"
        : "+f"(c[0]), "+f"(c[1]), "+f"(c[2]), "+f"(c[3])
        : "r"(a[0]), "r"(a[1]), "r"(a[2]), "r"(a[3]), "r"(b0), "r"(b1));
}

__device__ __forceinline__ uint32_t pack2(__half2 h) {
    uint32_t u;
    *reinterpret_cast<__half2*>(&u) = h;
    return u;
}

// ============================================================================
// Conversion kernels (8 elements / thread)
// ============================================================================
__global__ void __launch_bounds__(256) convert_x_kernel(const float* __restrict__ x) {
    size_t i = (size_t)blockIdx.x * 256 + threadIdx.x;
    const float4 a = reinterpret_cast<const float4*>(x)[2 * i];
    const float4 b = reinterpret_cast<const float4*>(x)[2 * i + 1];
    uint4 u;
    u.x = pack2(__floats2half2_rn(a.x, a.y));
    u.y = pack2(__floats2half2_rn(a.z, a.w));
    u.z = pack2(__floats2half2_rn(b.x, b.y));
    u.w = pack2(__floats2half2_rn(b.z, b.w));
    reinterpret_cast<uint4*>(g_xh)[i] = u;
}

__global__ void __launch_bounds__(256) convert_w_kernel(const int* __restrict__ w) {
    size_t i = (size_t)blockIdx.x * 256 + threadIdx.x;
    const int4 a = reinterpret_cast<const int4*>(w)[2 * i];
    const int4 b = reinterpret_cast<const int4*>(w)[2 * i + 1];
    uint4 u;
    u.x = pack2(__floats2half2_rn((float)a.x, (float)a.y));
    u.y = pack2(__floats2half2_rn((float)a.z, (float)a.w));
    u.z = pack2(__floats2half2_rn((float)b.x, (float)b.y));
    u.w = pack2(__floats2half2_rn((float)b.z, (float)b.w));
    reinterpret_cast<uint4*>(g_wh)[i] = u;
}

// ============================================================================
// GEMM: 256 threads, warp grid 2(M) x 4(N), warp tile 64x64, mma m16n8k16 fp16
// ============================================================================
__global__ void __launch_bounds__(256, 1)
gemm_kernel(const float* __restrict__ scale_p, const float* __restrict__ bias,
            float* __restrict__ out)
{
    extern __shared__ char smem[];
    const uint32_t sb = smem_u32(smem);
    const int tid = threadIdx.x;
    const int wid = tid >> 5;
    const int lane = tid & 31;
    const int wm = wid & 1;        // 0..1  (M)
    const int wn = wid >> 1;       // 0..3  (N)

    // CTA rasterization: group of 8 M-tiles per N sweep (L2 reuse on B)
    const int GROUP = 8;
    const int tpg = GROUP * NTN;
    const int b = blockIdx.x;
    const int g = b / tpg;
    const int rem = b - g * tpg;
    const int tm = g * GROUP + (rem % GROUP);
    const int tn = rem / GROUP;

    const __half* xa = g_xh + (size_t)tm * BM * KTOT;
    const __half* wb = g_wh + (size_t)tn * BN * KTOT;

    float acc[4][8][4];
#pragma unroll
    for (int mt = 0; mt < 4; mt++)
#pragma unroll
        for (int nt = 0; nt < 8; nt++)
#pragma unroll
            for (int q = 0; q < 4; q++) acc[mt][nt][q] = 0.f;

    // ---- async loader: one commit group per chunk ----
    auto load_chunk = [&](int stage, int chunk) {
        const uint32_t st = sb + stage * STAGE_BYTES;
        const int c0 = chunk * BK;
#pragma unroll
        for (int r = 0; r < 4; r++) {        // A: 128 rows x 128B
            int u = tid + r * 256;
            int row = u >> 3, col = (u & 7) * 8;
            cp16(st + sw128(u * 16), xa + (size_t)row * KTOT + c0 + col);
        }
#pragma unroll
        for (int r = 0; r < 8; r++) {        // B: 256 rows x 128B
            int u = tid + r * 256;
            int row = u >> 3, col = (u & 7) * 8;
            cp16(st + A_BYTES + sw128(u * 16), wb + (size_t)row * KTOT + c0 + col);
        }
        CP_COMMIT();
    };

    load_chunk(0, 0);
    load_chunk(1, 1);

    for (int i = 0; i < KCHUNKS; i++) {
        const int st = i % NSTAGE;
        if (i + 1 < KCHUNKS) { CP_WAIT(1); } else { CP_WAIT(0); }
        __syncthreads();
        if (i + 2 < KCHUNKS) load_chunk((i + 2) % NSTAGE, i + 2);

        const uint32_t abase = sb + st * STAGE_BYTES;
        const uint32_t bbase = abase + A_BYTES;

#pragma unroll
        for (int ks = 0; ks < 4; ks++) {
            const uint32_t koff = (ks * 16 + ((lane >> 4) * 8)) * 2;
            uint32_t bf[4][4];
#pragma unroll
            for (int gN = 0; gN < 4; gN++) {
                uint32_t o = (uint32_t)(wn * 64 + gN * 16 + (lane & 15)) * 128 + koff;
                ldsm4(bf[gN], bbase + sw128(o));
            }
#pragma unroll
            for (int mt = 0; mt < 4; mt++) {
                uint32_t af[4];
                uint32_t o = (uint32_t)(wm * 64 + mt * 16 + (lane & 15)) * 128 + koff;
                ldsm4(af, abase + sw128(o));
#pragma unroll
                for (int gN = 0; gN < 4; gN++) {
                    mma16816(acc[mt][2 * gN],     af, bf[gN][0], bf[gN][2]);
                    mma16816(acc[mt][2 * gN + 1], af, bf[gN][1], bf[gN][3]);
                }
            }
        }
    }

    // ---- epilogue: scale * acc + bias ----
    const float s = __ldg(scale_p);
    const int r0 = lane >> 2;
    const int c0 = (lane & 3) * 2;

#pragma unroll
    for (int mt = 0; mt < 4; mt++) {
        const int mrow = tm * BM + wm * 64 + mt * 16 + r0;
        float* orow = out + (size_t)mrow * NTOT;
#pragma unroll
        for (int nt = 0; nt < 8; nt++) {
            const int ncol = tn * BN + wn * 64 + nt * 8 + c0;
            const float b0 = __ldg(bias + ncol);
            const float b1 = __ldg(bias + ncol + 1);
            float2 v0, v1;
            v0.x = fmaf(s, acc[mt][nt][0], b0);
            v0.y = fmaf(s, acc[mt][nt][1], b1);
            v1.x = fmaf(s, acc[mt][nt][2], b0);
            v1.y = fmaf(s, acc[mt][nt][3], b1);
            *reinterpret_cast<float2*>(orow + ncol) = v0;
            *reinterpret_cast<float2*>(orow + 8 * (size_t)NTOT + ncol) = v1;
        }
    }
}

// ============================================================================
// Launch
// ============================================================================
extern "C" void kernel_launch(void* const* d_in, const int* in_sizes, int n_in,
                              void* d_out, int out_size) {
    const float* x     = (const float*)d_in[0];
    const int*   w     = (const int*)  d_in[1];
    const float* scale = (const float*)d_in[2];
    const float* bias  = (const float*)d_in[3];
    float* out = (float*)d_out;

    cudaFuncSetAttribute(gemm_kernel,
                         cudaFuncAttributeMaxDynamicSharedMemorySize, SMEM_TOTAL);

    convert_x_kernel<<<((size_t)MTOT * KTOT / 8) / 256, 256>>>(x);
    convert_w_kernel<<<((size_t)NTOT * KTOT / 8) / 256, 256>>>(w);
    gemm_kernel<<<NTM * NTN, 256, SMEM_TOTAL>>>(scale, bias, out);
}

// round 4
// speedup vs baseline: 1.0027x; 1.0027x over previous
#include <cuda_runtime.h>
#include <cuda_fp16.h>
#include <cstdint>

// ============================================================================
// Problem dims: out[M,N] = scale * x[M,K] @ W[N,K]^T + bias[N]
// ============================================================================
#define KTOT 4096
#define MTOT 8192   // 4 * 2048
#define NTOT 11008

constexpr int BM = 128, BN = 256, BK = 64;
constexpr int KCHUNKS = KTOT / BK;     // 64
constexpr int NTM = MTOT / BM;         // 64
constexpr int NTN = NTOT / BN;         // 43
constexpr int NSTAGE = 3;

constexpr int A_BYTES = BM * BK * 2;            // 16384
constexpr int B_BYTES = BN * BK * 2;            // 32768
constexpr int STAGE_BYTES = A_BYTES + B_BYTES;  // 49152
constexpr int SMEM_TOTAL = NSTAGE * STAGE_BYTES;// 147456

// ============================================================================
// Device scratch (no cudaMalloc allowed)
// ============================================================================
static __device__ __half g_xh[(size_t)MTOT * KTOT];   // 64 MB
static __device__ __half g_wh[(size_t)NTOT * KTOT];   // 86 MB

// ============================================================================
// Helpers (plain sm_103 PTX only: cp.async / ldmatrix / mma.sync)
// ============================================================================
__device__ __forceinline__ uint32_t smem_u32(const void* p) {
    return (uint32_t)__cvta_generic_to_shared(p);
}

__device__ __forceinline__ uint32_t sw128(uint32_t o) {
    return o ^ ((o >> 3) & 0x70);
}

__device__ __forceinline__ void cp16(uint32_t dst, const void* src) {
    asm volatile("cp.async.cg.shared.global [%0], [%1], 16;\n"
                 :: "r"(dst), "l"(src) : "memory");
}
#define CP_COMMIT() asm volatile("cp.async.commit_group;\n" ::: "memory")
#define CP_WAIT(N)  asm volatile("cp.async.wait_group %0;\n" :: "n"(N) : "memory")

__device__ __forceinline__ void ldsm4(uint32_t r[4], uint32_t addr) {
    asm volatile("ldmatrix.sync.aligned.m8n8.x4.shared.b16 {%0,%1,%2,%3}, [%4];"
                 : "=r"(r[0]), "=r"(r[1]), "=r"(r[2]), "=r"(r[3]) : "r"(addr));
}

__device__ __forceinline__ void mma16816(float c[4], const uint32_t a[4],
                                         uint32_t b0, uint32_t b1) {
    asm volatile(
        "mma.sync.aligned.m16n8k16.row.col.f32.f16.f16.f32 "
        "{%0,%1,%2,%3}, {%4,%5,%6,%7}, {%8,%9}, {%0,%1,%2,%3};"
        : "+f"(c[0]), "+f"(c[1]), "+f"(c[2]), "+f"(c[3])
        : "r"(a[0]), "r"(a[1]), "r"(a[2]), "r"(a[3]), "r"(b0), "r"(b1));
}

__device__ __forceinline__ uint32_t pack2(__half2 h) {
    uint32_t u;
    *reinterpret_cast<__half2*>(&u) = h;
    return u;
}

// ============================================================================
// Conversion kernels (8 elements / thread)
// ============================================================================
__global__ void __launch_bounds__(256) convert_x_kernel(const float* __restrict__ x) {
    size_t i = (size_t)blockIdx.x * 256 + threadIdx.x;
    const float4 a = reinterpret_cast<const float4*>(x)[2 * i];
    const float4 b = reinterpret_cast<const float4*>(x)[2 * i + 1];
    uint4 u;
    u.x = pack2(__floats2half2_rn(a.x, a.y));
    u.y = pack2(__floats2half2_rn(a.z, a.w));
    u.z = pack2(__floats2half2_rn(b.x, b.y));
    u.w = pack2(__floats2half2_rn(b.z, b.w));
    reinterpret_cast<uint4*>(g_xh)[i] = u;
}

__global__ void __launch_bounds__(256) convert_w_kernel(const int* __restrict__ w) {
    size_t i = (size_t)blockIdx.x * 256 + threadIdx.x;
    const int4 a = reinterpret_cast<const int4*>(w)[2 * i];
    const int4 b = reinterpret_cast<const int4*>(w)[2 * i + 1];
    uint4 u;
    u.x = pack2(__floats2half2_rn((float)a.x, (float)a.y));
    u.y = pack2(__floats2half2_rn((float)a.z, (float)a.w));
    u.z = pack2(__floats2half2_rn((float)b.x, (float)b.y));
    u.w = pack2(__floats2half2_rn((float)b.z, (float)b.w));
    reinterpret_cast<uint4*>(g_wh)[i] = u;
}

// ============================================================================
// GEMM: 256 threads, warp grid 2(M) x 4(N), warp tile 64x64, mma m16n8k16 fp16
// Register-level software pipelining: B double-buffered per ks, A per mt.
// ============================================================================
__global__ void __launch_bounds__(256, 1)
gemm_kernel(const float* __restrict__ scale_p, const float* __restrict__ bias,
            float* __restrict__ out)
{
    extern __shared__ char smem[];
    const uint32_t sb = smem_u32(smem);
    const int tid = threadIdx.x;
    const int wid = tid >> 5;
    const int lane = tid & 31;
    const int wm = wid & 1;        // 0..1  (M)
    const int wn = wid >> 1;       // 0..3  (N)

    // CTA rasterization: group of 8 M-tiles per N sweep (L2 reuse on B)
    const int GROUP = 8;
    const int tpg = GROUP * NTN;
    const int b = blockIdx.x;
    const int g = b / tpg;
    const int rem = b - g * tpg;
    const int tm = g * GROUP + (rem % GROUP);
    const int tn = rem / GROUP;

    const __half* xa = g_xh + (size_t)tm * BM * KTOT;
    const __half* wb = g_wh + (size_t)tn * BN * KTOT;

    float acc[4][8][4];
#pragma unroll
    for (int mt = 0; mt < 4; mt++)
#pragma unroll
        for (int nt = 0; nt < 8; nt++)
#pragma unroll
            for (int q = 0; q < 4; q++) acc[mt][nt][q] = 0.f;

    // ---- async loader: one commit group per chunk ----
    auto load_chunk = [&](int stage, int chunk) {
        const uint32_t st = sb + stage * STAGE_BYTES;
        const int c0 = chunk * BK;
#pragma unroll
        for (int r = 0; r < 4; r++) {        // A: 128 rows x 128B
            int u = tid + r * 256;
            int row = u >> 3, col = (u & 7) * 8;
            cp16(st + sw128(u * 16), xa + (size_t)row * KTOT + c0 + col);
        }
#pragma unroll
        for (int r = 0; r < 8; r++) {        // B: 256 rows x 128B
            int u = tid + r * 256;
            int row = u >> 3, col = (u & 7) * 8;
            cp16(st + A_BYTES + sw128(u * 16), wb + (size_t)row * KTOT + c0 + col);
        }
        CP_COMMIT();
    };

    load_chunk(0, 0);
    load_chunk(1, 1);

    // fragment double buffers
    uint32_t bfb[2][4][4];    // [buf][gN][4]
    uint32_t afb[2][4];       // [buf][4]

    // per-lane constant address pieces
    const uint32_t lrow = (uint32_t)(lane & 15) * 128;
    const uint32_t lk   = (uint32_t)(lane >> 4) * 16;   // bytes

    for (int i = 0; i < KCHUNKS; i++) {
        const int st = i % NSTAGE;
        if (i + 1 < KCHUNKS) { CP_WAIT(1); } else { CP_WAIT(0); }
        __syncthreads();
        if (i + 2 < KCHUNKS) load_chunk((i + 2) % NSTAGE, i + 2);

        const uint32_t abase = sb + st * STAGE_BYTES;
        const uint32_t bbase = abase + A_BYTES;

        auto ldA = [&](int buf, int ks, int mt) {
            uint32_t o = (uint32_t)(wm * 64 + mt * 16) * 128 + lrow
                       + (uint32_t)ks * 32 + lk;
            ldsm4(afb[buf], abase + sw128(o));
        };
        auto ldB = [&](int buf, int ks) {
#pragma unroll
            for (int gN = 0; gN < 4; gN++) {
                uint32_t o = (uint32_t)(wn * 64 + gN * 16) * 128 + lrow
                           + (uint32_t)ks * 32 + lk;
                ldsm4(bfb[buf][gN], bbase + sw128(o));
            }
        };

        // prime the register pipeline
        ldB(0, 0);
        ldA(0, 0, 0);

#pragma unroll
        for (int ks = 0; ks < 4; ks++) {
            if (ks < 3) ldB((ks + 1) & 1, ks + 1);
#pragma unroll
            for (int mt = 0; mt < 4; mt++) {
                const int p = ks * 4 + mt;
                if (mt < 3)           ldA((p + 1) & 1, ks, mt + 1);
                else if (ks < 3)      ldA((p + 1) & 1, ks + 1, 0);
                const uint32_t* af = afb[p & 1];
                const uint32_t (*bf)[4] = bfb[ks & 1];
#pragma unroll
                for (int gN = 0; gN < 4; gN++) {
                    mma16816(acc[mt][2 * gN],     af, bf[gN][0], bf[gN][2]);
                    mma16816(acc[mt][2 * gN + 1], af, bf[gN][1], bf[gN][3]);
                }
            }
        }
    }

    // ---- epilogue: scale * acc + bias ----
    const float s = __ldg(scale_p);
    const int r0 = lane >> 2;
    const int c0 = (lane & 3) * 2;

#pragma unroll
    for (int mt = 0; mt < 4; mt++) {
        const int mrow = tm * BM + wm * 64 + mt * 16 + r0;
        float* orow = out + (size_t)mrow * NTOT;
#pragma unroll
        for (int nt = 0; nt < 8; nt++) {
            const int ncol = tn * BN + wn * 64 + nt * 8 + c0;
            const float b0 = __ldg(bias + ncol);
            const float b1 = __ldg(bias + ncol + 1);
            float2 v0, v1;
            v0.x = fmaf(s, acc[mt][nt][0], b0);
            v0.y = fmaf(s, acc[mt][nt][1], b1);
            v1.x = fmaf(s, acc[mt][nt][2], b0);
            v1.y = fmaf(s, acc[mt][nt][3], b1);
            *reinterpret_cast<float2*>(orow + ncol) = v0;
            *reinterpret_cast<float2*>(orow + 8 * (size_t)NTOT + ncol) = v1;
        }
    }
}

// ============================================================================
// Launch
// ============================================================================
extern "C" void kernel_launch(void* const* d_in, const int* in_sizes, int n_in,
                              void* d_out, int out_size) {
    const float* x     = (const float*)d_in[0];
    const int*   w     = (const int*)  d_in[1];
    const float* scale = (const float*)d_in[2];
    const float* bias  = (const float*)d_in[3];
    float* out = (float*)d_out;

    cudaFuncSetAttribute(gemm_kernel,
                         cudaFuncAttributeMaxDynamicSharedMemorySize, SMEM_TOTAL);

    convert_x_kernel<<<((size_t)MTOT * KTOT / 8) / 256, 256>>>(x);
    convert_w_kernel<<<((size_t)NTOT * KTOT / 8) / 256, 256>>>(w);
    gemm_kernel<<<NTM * NTN, 256, SMEM_TOTAL>>>(scale, bias, out);
}

// round 5
// speedup vs baseline: 1.1516x; 1.1485x over previous
#include <cuda_runtime.h>
#include <cuda_fp16.h>
#include <cstdint>

// ============================================================================
// Problem dims: out[M,N] = scale * x[M,K] @ W[N,K]^T + bias[N]
// ============================================================================
#define KTOT 4096
#define MTOT 8192   // 4 * 2048
#define NTOT 11008

constexpr int BM = 128, BN = 128, BK = 64;
constexpr int KCHUNKS = KTOT / BK;     // 64
constexpr int NTM = MTOT / BM;         // 64
constexpr int NTN = NTOT / BN;         // 86
constexpr int NSTAGE = 3;

constexpr int A_BYTES = BM * BK * 2;            // 16384
constexpr int B_BYTES = BN * BK * 2;            // 16384
constexpr int STAGE_BYTES = A_BYTES + B_BYTES;  // 32768
constexpr int SMEM_TOTAL = NSTAGE * STAGE_BYTES;// 98304 per CTA -> 2 CTAs/SM

// ============================================================================
// Device scratch (no cudaMalloc allowed)
// ============================================================================
static __device__ __half g_xh[(size_t)MTOT * KTOT];   // 64 MB
static __device__ __half g_wh[(size_t)NTOT * KTOT];   // 86 MB

// ============================================================================
// Helpers (plain sm_103 PTX only: cp.async / ldmatrix / mma.sync)
// ============================================================================
__device__ __forceinline__ uint32_t smem_u32(const void* p) {
    return (uint32_t)__cvta_generic_to_shared(p);
}

__device__ __forceinline__ uint32_t sw128(uint32_t o) {
    return o ^ ((o >> 3) & 0x70);
}

__device__ __forceinline__ void cp16(uint32_t dst, const void* src) {
    asm volatile("cp.async.cg.shared.global [%0], [%1], 16;\n"
                 :: "r"(dst), "l"(src) : "memory");
}
#define CP_COMMIT() asm volatile("cp.async.commit_group;\n" ::: "memory")
#define CP_WAIT(N)  asm volatile("cp.async.wait_group %0;\n" :: "n"(N) : "memory")

__device__ __forceinline__ void ldsm4(uint32_t r[4], uint32_t addr) {
    asm volatile("ldmatrix.sync.aligned.m8n8.x4.shared.b16 {%0,%1,%2,%3}, [%4];"
                 : "=r"(r[0]), "=r"(r[1]), "=r"(r[2]), "=r"(r[3]) : "r"(addr));
}

__device__ __forceinline__ void mma16816(float c[4], const uint32_t a[4],
                                         uint32_t b0, uint32_t b1) {
    asm volatile(
        "mma.sync.aligned.m16n8k16.row.col.f32.f16.f16.f32 "
        "{%0,%1,%2,%3}, {%4,%5,%6,%7}, {%8,%9}, {%0,%1,%2,%3};"
        : "+f"(c[0]), "+f"(c[1]), "+f"(c[2]), "+f"(c[3])
        : "r"(a[0]), "r"(a[1]), "r"(a[2]), "r"(a[3]), "r"(b0), "r"(b1));
}

__device__ __forceinline__ uint32_t pack2(__half2 h) {
    uint32_t u;
    *reinterpret_cast<__half2*>(&u) = h;
    return u;
}

// ============================================================================
// Conversion kernels (8 elements / thread)
// ============================================================================
__global__ void __launch_bounds__(256) convert_x_kernel(const float* __restrict__ x) {
    size_t i = (size_t)blockIdx.x * 256 + threadIdx.x;
    const float4 a = reinterpret_cast<const float4*>(x)[2 * i];
    const float4 b = reinterpret_cast<const float4*>(x)[2 * i + 1];
    uint4 u;
    u.x = pack2(__floats2half2_rn(a.x, a.y));
    u.y = pack2(__floats2half2_rn(a.z, a.w));
    u.z = pack2(__floats2half2_rn(b.x, b.y));
    u.w = pack2(__floats2half2_rn(b.z, b.w));
    reinterpret_cast<uint4*>(g_xh)[i] = u;
}

__global__ void __launch_bounds__(256) convert_w_kernel(const int* __restrict__ w) {
    size_t i = (size_t)blockIdx.x * 256 + threadIdx.x;
    const int4 a = reinterpret_cast<const int4*>(w)[2 * i];
    const int4 b = reinterpret_cast<const int4*>(w)[2 * i + 1];
    uint4 u;
    u.x = pack2(__floats2half2_rn((float)a.x, (float)a.y));
    u.y = pack2(__floats2half2_rn((float)a.z, (float)a.w));
    u.z = pack2(__floats2half2_rn((float)b.x, (float)b.y));
    u.w = pack2(__floats2half2_rn((float)b.z, (float)b.w));
    reinterpret_cast<uint4*>(g_wh)[i] = u;
}

// ============================================================================
// GEMM: 256 threads, 2 CTAs/SM. Warp grid 2(M) x 4(N), warp tile 64x32.
// ============================================================================
__global__ void __launch_bounds__(256, 2)
gemm_kernel(const float* __restrict__ scale_p, const float* __restrict__ bias,
            float* __restrict__ out)
{
    extern __shared__ char smem[];
    const uint32_t sb = smem_u32(smem);
    const int tid = threadIdx.x;
    const int wid = tid >> 5;
    const int lane = tid & 31;
    const int wm = wid & 1;        // 0..1  (M)
    const int wn = wid >> 1;       // 0..3  (N)

    // CTA rasterization: group of 16 M-tiles per N sweep (L2 reuse on B)
    const int GROUP = 16;
    const int tpg = GROUP * NTN;
    const int b = blockIdx.x;
    const int g = b / tpg;
    const int rem = b - g * tpg;
    const int tm = g * GROUP + (rem % GROUP);
    const int tn = rem / GROUP;

    const __half* xa = g_xh + (size_t)tm * BM * KTOT;
    const __half* wb = g_wh + (size_t)tn * BN * KTOT;

    float acc[4][4][4];
#pragma unroll
    for (int mt = 0; mt < 4; mt++)
#pragma unroll
        for (int nt = 0; nt < 4; nt++)
#pragma unroll
            for (int q = 0; q < 4; q++) acc[mt][nt][q] = 0.f;

    // ---- async loader: one commit group per chunk ----
    auto load_chunk = [&](int stage, int chunk) {
        const uint32_t st = sb + stage * STAGE_BYTES;
        const int c0 = chunk * BK;
#pragma unroll
        for (int r = 0; r < 4; r++) {        // A: 128 rows x 128B
            int u = tid + r * 256;
            int row = u >> 3, col = (u & 7) * 8;
            cp16(st + sw128(u * 16), xa + (size_t)row * KTOT + c0 + col);
        }
#pragma unroll
        for (int r = 0; r < 4; r++) {        // B: 128 rows x 128B
            int u = tid + r * 256;
            int row = u >> 3, col = (u & 7) * 8;
            cp16(st + A_BYTES + sw128(u * 16), wb + (size_t)row * KTOT + c0 + col);
        }
        CP_COMMIT();
    };

    load_chunk(0, 0);
    load_chunk(1, 1);

    // fragment double buffers
    uint32_t bfb[2][2][4];    // [buf][gN][4]
    uint32_t afb[2][4];       // [buf][4]

    const uint32_t lrow = (uint32_t)(lane & 15) * 128;
    const uint32_t lk   = (uint32_t)(lane >> 4) * 16;   // bytes

    for (int i = 0; i < KCHUNKS; i++) {
        const int st = i % NSTAGE;
        if (i + 1 < KCHUNKS) { CP_WAIT(1); } else { CP_WAIT(0); }
        __syncthreads();
        if (i + 2 < KCHUNKS) load_chunk((i + 2) % NSTAGE, i + 2);

        const uint32_t abase = sb + st * STAGE_BYTES;
        const uint32_t bbase = abase + A_BYTES;

        auto ldA = [&](int buf, int ks, int mt) {
            uint32_t o = (uint32_t)(wm * 64 + mt * 16) * 128 + lrow
                       + (uint32_t)ks * 32 + lk;
            ldsm4(afb[buf], abase + sw128(o));
        };
        auto ldB = [&](int buf, int ks) {
#pragma unroll
            for (int gN = 0; gN < 2; gN++) {
                uint32_t o = (uint32_t)(wn * 32 + gN * 16) * 128 + lrow
                           + (uint32_t)ks * 32 + lk;
                ldsm4(bfb[buf][gN], bbase + sw128(o));
            }
        };

        ldB(0, 0);
        ldA(0, 0, 0);

#pragma unroll
        for (int ks = 0; ks < 4; ks++) {
            if (ks < 3) ldB((ks + 1) & 1, ks + 1);
#pragma unroll
            for (int mt = 0; mt < 4; mt++) {
                const int p = ks * 4 + mt;
                if (mt < 3)           ldA((p + 1) & 1, ks, mt + 1);
                else if (ks < 3)      ldA((p + 1) & 1, ks + 1, 0);
                const uint32_t* af = afb[p & 1];
                const uint32_t (*bf)[4] = bfb[ks & 1];
#pragma unroll
                for (int gN = 0; gN < 2; gN++) {
                    mma16816(acc[mt][2 * gN],     af, bf[gN][0], bf[gN][2]);
                    mma16816(acc[mt][2 * gN + 1], af, bf[gN][1], bf[gN][3]);
                }
            }
        }
    }

    // ---- epilogue: scale * acc + bias ----
    const float s = __ldg(scale_p);
    const int r0 = lane >> 2;
    const int c0 = (lane & 3) * 2;

#pragma unroll
    for (int mt = 0; mt < 4; mt++) {
        const int mrow = tm * BM + wm * 64 + mt * 16 + r0;
        float* orow = out + (size_t)mrow * NTOT;
#pragma unroll
        for (int nt = 0; nt < 4; nt++) {
            const int ncol = tn * BN + wn * 32 + nt * 8 + c0;
            const float b0 = __ldg(bias + ncol);
            const float b1 = __ldg(bias + ncol + 1);
            float2 v0, v1;
            v0.x = fmaf(s, acc[mt][nt][0], b0);
            v0.y = fmaf(s, acc[mt][nt][1], b1);
            v1.x = fmaf(s, acc[mt][nt][2], b0);
            v1.y = fmaf(s, acc[mt][nt][3], b1);
            *reinterpret_cast<float2*>(orow + ncol) = v0;
            *reinterpret_cast<float2*>(orow + 8 * (size_t)NTOT + ncol) = v1;
        }
    }
}

// ============================================================================
// Launch
// ============================================================================
extern "C" void kernel_launch(void* const* d_in, const int* in_sizes, int n_in,
                              void* d_out, int out_size) {
    const float* x     = (const float*)d_in[0];
    const int*   w     = (const int*)  d_in[1];
    const float* scale = (const float*)d_in[2];
    const float* bias  = (const float*)d_in[3];
    float* out = (float*)d_out;

    cudaFuncSetAttribute(gemm_kernel,
                         cudaFuncAttributeMaxDynamicSharedMemorySize, SMEM_TOTAL);

    convert_x_kernel<<<((size_t)MTOT * KTOT / 8) / 256, 256>>>(x);
    convert_w_kernel<<<((size_t)NTOT * KTOT / 8) / 256, 256>>>(w);
    gemm_kernel<<<NTM * NTN, 256, SMEM_TOTAL>>>(scale, bias, out);
}